// round 3
// baseline (speedup 1.0000x reference)
#include <cuda_runtime.h>
#include <cuda_bf16.h>
#include <cstdint>

using bf16 = __nv_bfloat16;

#define B_  8
#define C_  512
#define T_  2048
#define CQ_ 64

// ---------------------------------------------------------------------------
// Device-global scratch
// ---------------------------------------------------------------------------
__device__ bf16 g_xb [B_ * C_ * T_];
__device__ bf16 g_wqb[CQ_ * C_];
__device__ bf16 g_wkb[CQ_ * C_];
__device__ bf16 g_wvb[C_ * C_];
__device__ bf16 g_qb [B_ * CQ_ * T_];   // [B, Cq, T]
__device__ bf16 g_kb [B_ * CQ_ * T_];   // [B, Cq, T]
__device__ bf16 g_vb [B_ * C_  * T_];   // [B, C, T]

// ---------------------------------------------------------------------------
// PTX helpers
// ---------------------------------------------------------------------------
__device__ __forceinline__ uint32_t cvta_s(const void* p) {
    return (uint32_t)__cvta_generic_to_shared(p);
}
__device__ __forceinline__ void ldsm_x4(uint32_t* r, uint32_t a) {
    asm volatile("ldmatrix.sync.aligned.m8n8.x4.shared.b16 {%0,%1,%2,%3},[%4];"
                 : "=r"(r[0]), "=r"(r[1]), "=r"(r[2]), "=r"(r[3]) : "r"(a));
}
__device__ __forceinline__ void ldsm_x4t(uint32_t* r, uint32_t a) {
    asm volatile("ldmatrix.sync.aligned.m8n8.x4.trans.shared.b16 {%0,%1,%2,%3},[%4];"
                 : "=r"(r[0]), "=r"(r[1]), "=r"(r[2]), "=r"(r[3]) : "r"(a));
}
__device__ __forceinline__ void ldsm_x2(uint32_t* r, uint32_t a) {
    asm volatile("ldmatrix.sync.aligned.m8n8.x2.shared.b16 {%0,%1},[%2];"
                 : "=r"(r[0]), "=r"(r[1]) : "r"(a));
}
__device__ __forceinline__ void ldsm_x2t(uint32_t* r, uint32_t a) {
    asm volatile("ldmatrix.sync.aligned.m8n8.x2.trans.shared.b16 {%0,%1},[%2];"
                 : "=r"(r[0]), "=r"(r[1]) : "r"(a));
}
__device__ __forceinline__ void mma_bf16(float* c, const uint32_t* a, const uint32_t* b) {
    asm volatile("mma.sync.aligned.m16n8k16.row.col.f32.bf16.bf16.f32 "
                 "{%0,%1,%2,%3},{%4,%5,%6,%7},{%8,%9},{%0,%1,%2,%3};"
                 : "+f"(c[0]), "+f"(c[1]), "+f"(c[2]), "+f"(c[3])
                 : "r"(a[0]), "r"(a[1]), "r"(a[2]), "r"(a[3]), "r"(b[0]), "r"(b[1]));
}

// ---------------------------------------------------------------------------
// fp32 -> bf16 convert
// ---------------------------------------------------------------------------
__global__ void f2b_kernel(const float* __restrict__ in, bf16* __restrict__ out, int n4) {
    int i = blockIdx.x * blockDim.x + threadIdx.x;
    if (i >= n4) return;
    float4 v = *reinterpret_cast<const float4*>(in + (size_t)i * 4);
    __nv_bfloat162 lo = __floats2bfloat162_rn(v.x, v.y);
    __nv_bfloat162 hi = __floats2bfloat162_rn(v.z, v.w);
    uint2 pk;
    pk.x = *reinterpret_cast<uint32_t*>(&lo);
    pk.y = *reinterpret_cast<uint32_t*>(&hi);
    *reinterpret_cast<uint2*>(out + (size_t)i * 4) = pk;
}

// ---------------------------------------------------------------------------
// Projection: O[b,m,t] (bf16) = sum_k W[m,k]*X[b,k,t] + bias[m]
// (unchanged from round 2 — validated)
// ---------------------------------------------------------------------------
__global__ void proj_mma(const bf16* __restrict__ W, const float* __restrict__ bias,
                         const bf16* __restrict__ X, bf16* __restrict__ O,
                         int M, int K)
{
    __shared__ bf16 sA[64][72];
    __shared__ bf16 sB[64][136];

    const int b  = blockIdx.z;
    const int n0 = blockIdx.x * 128;
    const int m0 = blockIdx.y * 64;
    const bf16* Xb = X + (size_t)b * K * T_;
    bf16*       Ob = O + (size_t)b * M * T_;

    const int tid  = threadIdx.x;
    const int lane = tid & 31;
    const int w    = tid >> 5;
    const int wm   = (w >> 2) * 32;
    const int wn   = (w & 3) * 32;

    float acc[2][4][4] = {};

    for (int kc = 0; kc < K; kc += 64) {
        {
            int r = tid >> 3, c = (tid & 7) * 8;
            #pragma unroll
            for (int p = 0; p < 2; p++)
                *reinterpret_cast<uint4*>(&sA[r + p * 32][c]) =
                    *reinterpret_cast<const uint4*>(&W[(size_t)(m0 + r + p * 32) * K + kc + c]);
        }
        {
            int r = tid >> 4, c = (tid & 15) * 8;
            #pragma unroll
            for (int p = 0; p < 4; p++)
                *reinterpret_cast<uint4*>(&sB[r + p * 16][c]) =
                    *reinterpret_cast<const uint4*>(&Xb[(size_t)(kc + r + p * 16) * T_ + n0 + c]);
        }
        __syncthreads();

        #pragma unroll
        for (int kk = 0; kk < 64; kk += 16) {
            uint32_t af[2][4], bf_[4][2];
            #pragma unroll
            for (int mi = 0; mi < 2; mi++) {
                uint32_t a = cvta_s(&sA[wm + mi * 16 + (lane & 15)][kk + (lane >> 4) * 8]);
                ldsm_x4(af[mi], a);
            }
            #pragma unroll
            for (int ni = 0; ni < 4; ni++) {
                int r = kk + ((lane >> 3) & 1) * 8 + (lane & 7);
                uint32_t a = cvta_s(&sB[r][wn + ni * 8]);
                ldsm_x2t(bf_[ni], a);
            }
            #pragma unroll
            for (int mi = 0; mi < 2; mi++)
                #pragma unroll
                for (int ni = 0; ni < 4; ni++)
                    mma_bf16(acc[mi][ni], af[mi], bf_[ni]);
        }
        __syncthreads();
    }

    #pragma unroll
    for (int mi = 0; mi < 2; mi++) {
        int grow = m0 + wm + mi * 16 + (lane >> 2);
        float bv0 = bias[grow];
        float bv1 = bias[grow + 8];
        #pragma unroll
        for (int ni = 0; ni < 4; ni++) {
            int gcol = n0 + wn + ni * 8 + (lane & 3) * 2;
            __nv_bfloat162 v0 = __floats2bfloat162_rn(acc[mi][ni][0] + bv0, acc[mi][ni][1] + bv0);
            __nv_bfloat162 v1 = __floats2bfloat162_rn(acc[mi][ni][2] + bv1, acc[mi][ni][3] + bv1);
            *reinterpret_cast<__nv_bfloat162*>(&Ob[(size_t)grow * T_ + gcol]) = v0;
            *reinterpret_cast<__nv_bfloat162*>(&Ob[(size_t)(grow + 8) * T_ + gcol]) = v1;
        }
    }
}

// ---------------------------------------------------------------------------
// Fused attention: per block (b, 128 t-rows, 256 c-cols)
//   loop s-chunks of 128: S = Q^T K -> exp -> sP(bf16) + row sums -> acc += P V^T
//   epilogue: out = gamma * acc / rowsum + x
// 512 threads = 16 warps (4 m-warps x 4 n-warps)
// ---------------------------------------------------------------------------
#define SQ_OFF   0u
#define SK_OFF   17408u
#define SP_OFF   34816u
#define SV_OFF   69632u
#define SRED_OFF 139264u
#define SINV_OFF 141312u
#define SMEM_TOT 141824u

__global__ void __launch_bounds__(512, 1)
fused_attn(const bf16* __restrict__ Q, const bf16* __restrict__ Kb,
           const bf16* __restrict__ V, const float* __restrict__ x,
           const float* __restrict__ gamma, float* __restrict__ O)
{
    extern __shared__ char smem[];
    bf16*  sQ   = reinterpret_cast<bf16*>(smem + SQ_OFF);    // [64][136]  (o, t)
    bf16*  sK   = reinterpret_cast<bf16*>(smem + SK_OFF);    // [64][136]  (o, s)
    bf16*  sP   = reinterpret_cast<bf16*>(smem + SP_OFF);    // [128][136] (t, s)
    bf16*  sV   = reinterpret_cast<bf16*>(smem + SV_OFF);    // [256][136] (c, s)
    float* sRed = reinterpret_cast<float*>(smem + SRED_OFF); // [4][128]
    float* sInv = reinterpret_cast<float*>(smem + SINV_OFF); // [128]

    const int b  = blockIdx.z;
    const int t0 = blockIdx.y * 128;
    const int c0 = blockIdx.x * 256;

    const bf16* Qb = Q  + (size_t)b * CQ_ * T_;
    const bf16* Kg = Kb + (size_t)b * CQ_ * T_;
    const bf16* Vg = V  + (size_t)b * C_  * T_;

    const int tid  = threadIdx.x;
    const int lane = tid & 31;
    const int w    = tid >> 5;
    const int wm   = (w >> 2) * 32;   // t within tile
    const int wn   = (w & 3) * 32;    // s within chunk (S mma)
    const int wno  = (w & 3) * 64;    // c within chunk (out mma)

    // Load Q tile: [64 o][128 t]
    {
        #pragma unroll
        for (int i = 0; i < 2; i++) {
            int u = tid * 2 + i;            // 0..1023
            int r = u >> 4, cp = (u & 15) * 8;
            *reinterpret_cast<uint4*>(&sQ[r * 136 + cp]) =
                *reinterpret_cast<const uint4*>(&Qb[(size_t)r * T_ + t0 + cp]);
        }
    }

    float acc[2][8][4] = {};      // out accumulators: [mi][ni(c)][4]
    float srow[2][2] = {};        // row-sum partials: [mi][h]

    for (int s0 = 0; s0 < T_; s0 += 128) {
        __syncthreads();   // previous iteration's reads of sK/sV/sP complete

        // Load K chunk [64 o][128 s]
        #pragma unroll
        for (int i = 0; i < 2; i++) {
            int u = tid + i * 512;
            int r = u >> 4, cp = (u & 15) * 8;
            *reinterpret_cast<uint4*>(&sK[r * 136 + cp]) =
                *reinterpret_cast<const uint4*>(&Kg[(size_t)r * T_ + s0 + cp]);
        }
        // Load V chunk [256 c][128 s]
        #pragma unroll
        for (int i = 0; i < 8; i++) {
            int u = tid + i * 512;
            int r = u >> 4, cp = (u & 15) * 8;
            *reinterpret_cast<uint4*>(&sV[r * 136 + cp]) =
                *reinterpret_cast<const uint4*>(&Vg[(size_t)(c0 + r) * T_ + s0 + cp]);
        }
        __syncthreads();

        // ---- S = Q^T K  (128t x 128s, k=64) ----
        float accS[2][4][4] = {};
        #pragma unroll
        for (int kk = 0; kk < 64; kk += 16) {
            uint32_t af[2][4], bf_[4][2];
            int g = lane >> 3;
            #pragma unroll
            for (int mi = 0; mi < 2; mi++) {
                uint32_t a = cvta_s(&sQ[(kk + (g >> 1) * 8 + (lane & 7)) * 136 +
                                        wm + mi * 16 + (g & 1) * 8]);
                ldsm_x4t(af[mi], a);
            }
            #pragma unroll
            for (int ni = 0; ni < 4; ni++) {
                int r = kk + ((lane >> 3) & 1) * 8 + (lane & 7);
                uint32_t a = cvta_s(&sK[r * 136 + wn + ni * 8]);
                ldsm_x2t(bf_[ni], a);
            }
            #pragma unroll
            for (int mi = 0; mi < 2; mi++)
                #pragma unroll
                for (int ni = 0; ni < 4; ni++)
                    mma_bf16(accS[mi][ni], af[mi], bf_[ni]);
        }

        // ---- exp, row-sum partials, write sP (bf16) ----
        #pragma unroll
        for (int mi = 0; mi < 2; mi++) {
            int r0 = wm + mi * 16 + (lane >> 2);
            #pragma unroll
            for (int ni = 0; ni < 4; ni++) {
                float p0 = __expf(accS[mi][ni][0]);
                float p1 = __expf(accS[mi][ni][1]);
                float p2 = __expf(accS[mi][ni][2]);
                float p3 = __expf(accS[mi][ni][3]);
                srow[mi][0] += p0 + p1;
                srow[mi][1] += p2 + p3;
                int cc = wn + ni * 8 + (lane & 3) * 2;
                __nv_bfloat162 lo = __floats2bfloat162_rn(p0, p1);
                __nv_bfloat162 hi = __floats2bfloat162_rn(p2, p3);
                *reinterpret_cast<__nv_bfloat162*>(&sP[r0 * 136 + cc]) = lo;
                *reinterpret_cast<__nv_bfloat162*>(&sP[(r0 + 8) * 136 + cc]) = hi;
            }
        }
        __syncthreads();

        // ---- acc += P (128t x 128s) * V^T (s x 256c) ----
        #pragma unroll
        for (int kk = 0; kk < 128; kk += 16) {
            uint32_t af[2][4], bf_[8][2];
            #pragma unroll
            for (int mi = 0; mi < 2; mi++) {
                uint32_t a = cvta_s(&sP[(wm + mi * 16 + (lane & 15)) * 136 +
                                        kk + (lane >> 4) * 8]);
                ldsm_x4(af[mi], a);
            }
            #pragma unroll
            for (int ni = 0; ni < 8; ni++) {
                uint32_t a = cvta_s(&sV[(wno + ni * 8 + (lane & 7)) * 136 +
                                        kk + ((lane >> 3) & 1) * 8]);
                ldsm_x2(bf_[ni], a);
            }
            #pragma unroll
            for (int mi = 0; mi < 2; mi++)
                #pragma unroll
                for (int ni = 0; ni < 8; ni++)
                    mma_bf16(acc[mi][ni], af[mi], bf_[ni]);
        }
    }
    __syncthreads();

    // ---- reduce row sums across lanes and n-warps ----
    #pragma unroll
    for (int mi = 0; mi < 2; mi++)
        #pragma unroll
        for (int h = 0; h < 2; h++) {
            float v = srow[mi][h];
            v += __shfl_xor_sync(0xffffffffu, v, 1);
            v += __shfl_xor_sync(0xffffffffu, v, 2);
            if ((lane & 3) == 0)
                sRed[(w & 3) * 128 + wm + mi * 16 + h * 8 + (lane >> 2)] = v;
        }
    __syncthreads();
    if (tid < 128) {
        float tot = sRed[tid] + sRed[128 + tid] + sRed[256 + tid] + sRed[384 + tid];
        sInv[tid] = 1.0f / tot;
    }
    __syncthreads();

    // ---- epilogue: out[b][c][t] = gamma * acc * inv + x ----
    const float gm = gamma[0];
    const size_t baseB = (size_t)b * C_ * T_;
    #pragma unroll
    for (int mi = 0; mi < 2; mi++) {
        int rl = wm + mi * 16 + (lane >> 2);
        float inv_lo = sInv[rl];
        float inv_hi = sInv[rl + 8];
        int t_lo = t0 + rl;
        int t_hi = t_lo + 8;
        #pragma unroll
        for (int ni = 0; ni < 8; ni++) {
            int c = c0 + wno + ni * 8 + (lane & 3) * 2;
            size_t i00 = baseB + (size_t)c * T_ + t_lo;
            size_t i01 = baseB + (size_t)(c + 1) * T_ + t_lo;
            size_t i10 = baseB + (size_t)c * T_ + t_hi;
            size_t i11 = baseB + (size_t)(c + 1) * T_ + t_hi;
            O[i00] = gm * acc[mi][ni][0] * inv_lo + x[i00];
            O[i01] = gm * acc[mi][ni][1] * inv_lo + x[i01];
            O[i10] = gm * acc[mi][ni][2] * inv_hi + x[i10];
            O[i11] = gm * acc[mi][ni][3] * inv_hi + x[i11];
        }
    }
}

// ---------------------------------------------------------------------------
// Launch
// ---------------------------------------------------------------------------
extern "C" void kernel_launch(void* const* d_in, const int* in_sizes, int n_in,
                              void* d_out, int out_size)
{
    const float* x     = (const float*)d_in[0];
    const float* wq    = (const float*)d_in[1];
    const float* bq    = (const float*)d_in[2];
    const float* wk    = (const float*)d_in[3];
    const float* bk    = (const float*)d_in[4];
    const float* wv    = (const float*)d_in[5];
    const float* bv    = (const float*)d_in[6];
    const float* gamma = (const float*)d_in[7];
    float* out = (float*)d_out;

    bf16 *xb, *wqb, *wkb, *wvb, *qb, *kb, *vb;
    cudaGetSymbolAddress((void**)&xb,  g_xb);
    cudaGetSymbolAddress((void**)&wqb, g_wqb);
    cudaGetSymbolAddress((void**)&wkb, g_wkb);
    cudaGetSymbolAddress((void**)&wvb, g_wvb);
    cudaGetSymbolAddress((void**)&qb,  g_qb);
    cudaGetSymbolAddress((void**)&kb,  g_kb);
    cudaGetSymbolAddress((void**)&vb,  g_vb);

    static bool attr_set = false;
    if (!attr_set) {
        cudaFuncSetAttribute(fused_attn, cudaFuncAttributeMaxDynamicSharedMemorySize, SMEM_TOT);
        attr_set = true;
    }

    // converts
    {
        int n4 = (B_ * C_ * T_) / 4;
        f2b_kernel<<<(n4 + 255) / 256, 256>>>(x, xb, n4);
        n4 = (CQ_ * C_) / 4;
        f2b_kernel<<<(n4 + 255) / 256, 256>>>(wq, wqb, n4);
        f2b_kernel<<<(n4 + 255) / 256, 256>>>(wk, wkb, n4);
        n4 = (C_ * C_) / 4;
        f2b_kernel<<<(n4 + 255) / 256, 256>>>(wv, wvb, n4);
    }

    // projections
    proj_mma<<<dim3(T_ / 128, CQ_ / 64, B_), 256>>>(wqb, bq, xb, qb, CQ_, C_);
    proj_mma<<<dim3(T_ / 128, CQ_ / 64, B_), 256>>>(wkb, bk, xb, kb, CQ_, C_);
    proj_mma<<<dim3(T_ / 128, C_  / 64, B_), 256>>>(wvb, bv, xb, vb, C_,  C_);

    // fused attention
    fused_attn<<<dim3(C_ / 256, T_ / 128, B_), 512, SMEM_TOT>>>(qb, kb, vb, x, gamma, out);
}

// round 4
// speedup vs baseline: 1.2475x; 1.2475x over previous
#include <cuda_runtime.h>
#include <cuda_bf16.h>
#include <cstdint>

using bf16 = __nv_bfloat16;

#define B_  8
#define C_  512
#define T_  2048
#define CQ_ 64

// ---------------------------------------------------------------------------
// Device-global scratch
// ---------------------------------------------------------------------------
__device__ bf16  g_xb [B_ * C_ * T_];
__device__ bf16  g_wqb[CQ_ * C_];
__device__ bf16  g_wkb[CQ_ * C_];
__device__ bf16  g_wvb[C_ * C_];
__device__ bf16  g_qb [B_ * CQ_ * T_];          // [B, Cq, T]
__device__ bf16  g_kb [B_ * CQ_ * T_];          // [B, Cq, T]
__device__ bf16  g_vb [B_ * C_  * T_];          // [B, C, T]
__device__ bf16  g_p  [(size_t)B_ * T_ * T_];   // unnormalized probs bf16
__device__ float g_rs [B_ * 16 * T_];           // partial row sums [b][sblk][t]
__device__ float g_inv[B_ * T_];                // 1 / row sum

// ---------------------------------------------------------------------------
// PTX helpers
// ---------------------------------------------------------------------------
__device__ __forceinline__ uint32_t cvta_s(const void* p) {
    return (uint32_t)__cvta_generic_to_shared(p);
}
__device__ __forceinline__ void ldsm_x4(uint32_t* r, uint32_t a) {
    asm volatile("ldmatrix.sync.aligned.m8n8.x4.shared.b16 {%0,%1,%2,%3},[%4];"
                 : "=r"(r[0]), "=r"(r[1]), "=r"(r[2]), "=r"(r[3]) : "r"(a));
}
__device__ __forceinline__ void ldsm_x4t(uint32_t* r, uint32_t a) {
    asm volatile("ldmatrix.sync.aligned.m8n8.x4.trans.shared.b16 {%0,%1,%2,%3},[%4];"
                 : "=r"(r[0]), "=r"(r[1]), "=r"(r[2]), "=r"(r[3]) : "r"(a));
}
__device__ __forceinline__ void ldsm_x2(uint32_t* r, uint32_t a) {
    asm volatile("ldmatrix.sync.aligned.m8n8.x2.shared.b16 {%0,%1},[%2];"
                 : "=r"(r[0]), "=r"(r[1]) : "r"(a));
}
__device__ __forceinline__ void ldsm_x2t(uint32_t* r, uint32_t a) {
    asm volatile("ldmatrix.sync.aligned.m8n8.x2.trans.shared.b16 {%0,%1},[%2];"
                 : "=r"(r[0]), "=r"(r[1]) : "r"(a));
}
__device__ __forceinline__ void mma_bf16(float* c, const uint32_t* a, const uint32_t* b) {
    asm volatile("mma.sync.aligned.m16n8k16.row.col.f32.bf16.bf16.f32 "
                 "{%0,%1,%2,%3},{%4,%5,%6,%7},{%8,%9},{%0,%1,%2,%3};"
                 : "+f"(c[0]), "+f"(c[1]), "+f"(c[2]), "+f"(c[3])
                 : "r"(a[0]), "r"(a[1]), "r"(a[2]), "r"(a[3]), "r"(b[0]), "r"(b[1]));
}

// ---------------------------------------------------------------------------
// fp32 -> bf16 converts
// ---------------------------------------------------------------------------
__device__ __forceinline__ void cvt4(const float* in, bf16* out, int i) {
    float4 v = *reinterpret_cast<const float4*>(in + (size_t)i * 4);
    __nv_bfloat162 lo = __floats2bfloat162_rn(v.x, v.y);
    __nv_bfloat162 hi = __floats2bfloat162_rn(v.z, v.w);
    uint2 pk;
    pk.x = *reinterpret_cast<uint32_t*>(&lo);
    pk.y = *reinterpret_cast<uint32_t*>(&hi);
    *reinterpret_cast<uint2*>(out + (size_t)i * 4) = pk;
}
__global__ void f2b_kernel(const float* __restrict__ in, bf16* __restrict__ out, int n4) {
    int i = blockIdx.x * blockDim.x + threadIdx.x;
    if (i < n4) cvt4(in, out, i);
}
// all three weight tensors in one launch
__global__ void f2b_w(const float* __restrict__ a, bf16* __restrict__ ao, int na4,
                      const float* __restrict__ b, bf16* __restrict__ bo, int nb4,
                      const float* __restrict__ c, bf16* __restrict__ co, int nc4) {
    int i = blockIdx.x * blockDim.x + threadIdx.x;
    if (i < na4)                    cvt4(a, ao, i);
    else if (i < na4 + nb4)         cvt4(b, bo, i - na4);
    else if (i < na4 + nb4 + nc4)   cvt4(c, co, i - na4 - nb4);
}

// ---------------------------------------------------------------------------
// Projection: O[b,m,t] (bf16) = sum_k W[m,k]*X[b,k,t] + bias[m]   (validated)
// ---------------------------------------------------------------------------
__global__ void proj_mma(const bf16* __restrict__ W, const float* __restrict__ bias,
                         const bf16* __restrict__ X, bf16* __restrict__ O,
                         int M, int K)
{
    __shared__ bf16 sA[64][72];
    __shared__ bf16 sB[64][136];

    const int b  = blockIdx.z;
    const int n0 = blockIdx.x * 128;
    const int m0 = blockIdx.y * 64;
    const bf16* Xb = X + (size_t)b * K * T_;
    bf16*       Ob = O + (size_t)b * M * T_;

    const int tid  = threadIdx.x;
    const int lane = tid & 31;
    const int w    = tid >> 5;
    const int wm   = (w >> 2) * 32;
    const int wn   = (w & 3) * 32;

    float acc[2][4][4] = {};

    for (int kc = 0; kc < K; kc += 64) {
        {
            int r = tid >> 3, c = (tid & 7) * 8;
            #pragma unroll
            for (int p = 0; p < 2; p++)
                *reinterpret_cast<uint4*>(&sA[r + p * 32][c]) =
                    *reinterpret_cast<const uint4*>(&W[(size_t)(m0 + r + p * 32) * K + kc + c]);
        }
        {
            int r = tid >> 4, c = (tid & 15) * 8;
            #pragma unroll
            for (int p = 0; p < 4; p++)
                *reinterpret_cast<uint4*>(&sB[r + p * 16][c]) =
                    *reinterpret_cast<const uint4*>(&Xb[(size_t)(kc + r + p * 16) * T_ + n0 + c]);
        }
        __syncthreads();

        #pragma unroll
        for (int kk = 0; kk < 64; kk += 16) {
            uint32_t af[2][4], bf_[4][2];
            #pragma unroll
            for (int mi = 0; mi < 2; mi++) {
                uint32_t a = cvta_s(&sA[wm + mi * 16 + (lane & 15)][kk + (lane >> 4) * 8]);
                ldsm_x4(af[mi], a);
            }
            #pragma unroll
            for (int ni = 0; ni < 4; ni++) {
                int r = kk + ((lane >> 3) & 1) * 8 + (lane & 7);
                uint32_t a = cvta_s(&sB[r][wn + ni * 8]);
                ldsm_x2t(bf_[ni], a);
            }
            #pragma unroll
            for (int mi = 0; mi < 2; mi++)
                #pragma unroll
                for (int ni = 0; ni < 4; ni++)
                    mma_bf16(acc[mi][ni], af[mi], bf_[ni]);
        }
        __syncthreads();
    }

    #pragma unroll
    for (int mi = 0; mi < 2; mi++) {
        int grow = m0 + wm + mi * 16 + (lane >> 2);
        float bv0 = bias[grow];
        float bv1 = bias[grow + 8];
        #pragma unroll
        for (int ni = 0; ni < 4; ni++) {
            int gcol = n0 + wn + ni * 8 + (lane & 3) * 2;
            __nv_bfloat162 v0 = __floats2bfloat162_rn(acc[mi][ni][0] + bv0, acc[mi][ni][1] + bv0);
            __nv_bfloat162 v1 = __floats2bfloat162_rn(acc[mi][ni][2] + bv1, acc[mi][ni][3] + bv1);
            *reinterpret_cast<__nv_bfloat162*>(&Ob[(size_t)grow * T_ + gcol]) = v0;
            *reinterpret_cast<__nv_bfloat162*>(&Ob[(size_t)(grow + 8) * T_ + gcol]) = v1;
        }
    }
}

// ---------------------------------------------------------------------------
// Scores + exp: P~[b,t,s] = exp(sum_o Q[b,o,t]K[b,o,s])  (bf16, unnormalized)
// Also emits partial row sums: g_rs[b][sblk][t] = sum over this block's 128 s.
// ---------------------------------------------------------------------------
__global__ void score_exp(const bf16* __restrict__ Q, const bf16* __restrict__ Km,
                          bf16* __restrict__ P, float* __restrict__ partial)
{
    __shared__ bf16 sA[64][72];    // [k=o][m=t]
    __shared__ bf16 sB[64][136];   // [k=o][n=s]
    __shared__ float red[4][64];

    const int b  = blockIdx.z;
    const int n0 = blockIdx.x * 128;
    const int m0 = blockIdx.y * 64;
    const bf16* Qb = Q  + (size_t)b * CQ_ * T_;
    const bf16* Kb = Km + (size_t)b * CQ_ * T_;

    const int tid  = threadIdx.x;
    const int lane = tid & 31;
    const int w    = tid >> 5;
    const int wm   = (w >> 2) * 32;
    const int wn   = (w & 3) * 32;

    {
        int r = tid >> 3, c = (tid & 7) * 8;
        #pragma unroll
        for (int p = 0; p < 2; p++)
            *reinterpret_cast<uint4*>(&sA[r + p * 32][c]) =
                *reinterpret_cast<const uint4*>(&Qb[(size_t)(r + p * 32) * T_ + m0 + c]);
    }
    {
        int r = tid >> 4, c = (tid & 15) * 8;
        #pragma unroll
        for (int p = 0; p < 4; p++)
            *reinterpret_cast<uint4*>(&sB[r + p * 16][c]) =
                *reinterpret_cast<const uint4*>(&Kb[(size_t)(r + p * 16) * T_ + n0 + c]);
    }
    __syncthreads();

    float acc[2][4][4] = {};

    #pragma unroll
    for (int kk = 0; kk < 64; kk += 16) {
        uint32_t af[2][4], bf_[4][2];
        int g = lane >> 3;
        #pragma unroll
        for (int mi = 0; mi < 2; mi++) {
            uint32_t a = cvta_s(&sA[kk + (g >> 1) * 8 + (lane & 7)][wm + mi * 16 + (g & 1) * 8]);
            ldsm_x4t(af[mi], a);
        }
        #pragma unroll
        for (int ni = 0; ni < 4; ni++) {
            int r = kk + ((lane >> 3) & 1) * 8 + (lane & 7);
            uint32_t a = cvta_s(&sB[r][wn + ni * 8]);
            ldsm_x2t(bf_[ni], a);
        }
        #pragma unroll
        for (int mi = 0; mi < 2; mi++)
            #pragma unroll
            for (int ni = 0; ni < 4; ni++)
                mma_bf16(acc[mi][ni], af[mi], bf_[ni]);
    }

    // exp + write bf16 P~ + partial row sums
    bf16* Pb = P + (size_t)b * T_ * T_;
    float rs[2][2] = {};
    #pragma unroll
    for (int mi = 0; mi < 2; mi++) {
        int grow = m0 + wm + mi * 16 + (lane >> 2);
        #pragma unroll
        for (int ni = 0; ni < 4; ni++) {
            float p0 = __expf(acc[mi][ni][0]);
            float p1 = __expf(acc[mi][ni][1]);
            float p2 = __expf(acc[mi][ni][2]);
            float p3 = __expf(acc[mi][ni][3]);
            rs[mi][0] += p0 + p1;
            rs[mi][1] += p2 + p3;
            int gcol = n0 + wn + ni * 8 + (lane & 3) * 2;
            __nv_bfloat162 lo = __floats2bfloat162_rn(p0, p1);
            __nv_bfloat162 hi = __floats2bfloat162_rn(p2, p3);
            *reinterpret_cast<__nv_bfloat162*>(&Pb[(size_t)grow * T_ + gcol]) = lo;
            *reinterpret_cast<__nv_bfloat162*>(&Pb[(size_t)(grow + 8) * T_ + gcol]) = hi;
        }
    }
    // reduce across lane&3 then across the 4 n-warps
    #pragma unroll
    for (int mi = 0; mi < 2; mi++)
        #pragma unroll
        for (int h = 0; h < 2; h++) {
            float v = rs[mi][h];
            v += __shfl_xor_sync(0xffffffffu, v, 1);
            v += __shfl_xor_sync(0xffffffffu, v, 2);
            if ((lane & 3) == 0)
                red[w & 3][wm + mi * 16 + h * 8 + (lane >> 2)] = v;
        }
    __syncthreads();
    if (tid < 64) {
        float tot = red[0][tid] + red[1][tid] + red[2][tid] + red[3][tid];
        partial[((size_t)b * 16 + blockIdx.x) * T_ + m0 + tid] = tot;
    }
}

// ---------------------------------------------------------------------------
// inv[b,t] = 1 / sum over 16 partials
// ---------------------------------------------------------------------------
__global__ void inv_rs(const float* __restrict__ partial, float* __restrict__ inv) {
    int idx = blockIdx.x * 256 + threadIdx.x;       // 0 .. B*T-1
    int b = idx >> 11;
    int t = idx & (T_ - 1);
    const float* p = partial + (size_t)b * 16 * T_ + t;
    float s = 0.0f;
    #pragma unroll
    for (int j = 0; j < 16; j++) s += p[j * T_];
    inv[idx] = 1.0f / s;
}

// ---------------------------------------------------------------------------
// Output: O[b,c,t] = gamma * inv[b,t] * sum_s V[b,c,s]*P~[b,t,s] + x[b,c,t]
// ---------------------------------------------------------------------------
__global__ void out_mma(const bf16* __restrict__ V, const bf16* __restrict__ P,
                        const float* __restrict__ inv,
                        const float* __restrict__ x, const float* __restrict__ gamma,
                        float* __restrict__ O)
{
    __shared__ bf16 sA[64][72];    // [m=c][k=s]
    __shared__ bf16 sB[128][72];   // [n=t][k=s]

    const int b  = blockIdx.z;
    const int n0 = blockIdx.x * 128;
    const int m0 = blockIdx.y * 64;
    const bf16* Vb = V + (size_t)b * C_ * T_;
    const bf16* Pb = P + (size_t)b * T_ * T_;

    const int tid  = threadIdx.x;
    const int lane = tid & 31;
    const int w    = tid >> 5;
    const int wm   = (w >> 2) * 32;
    const int wn   = (w & 3) * 32;

    float acc[2][4][4] = {};

    for (int kc = 0; kc < T_; kc += 64) {
        {
            int r = tid >> 3, c = (tid & 7) * 8;
            #pragma unroll
            for (int p = 0; p < 2; p++)
                *reinterpret_cast<uint4*>(&sA[r + p * 32][c]) =
                    *reinterpret_cast<const uint4*>(&Vb[(size_t)(m0 + r + p * 32) * T_ + kc + c]);
        }
        {
            int r = tid >> 3, c = (tid & 7) * 8;
            #pragma unroll
            for (int p = 0; p < 4; p++)
                *reinterpret_cast<uint4*>(&sB[r + p * 32][c]) =
                    *reinterpret_cast<const uint4*>(&Pb[(size_t)(n0 + r + p * 32) * T_ + kc + c]);
        }
        __syncthreads();

        #pragma unroll
        for (int kk = 0; kk < 64; kk += 16) {
            uint32_t af[2][4], bf_[4][2];
            #pragma unroll
            for (int mi = 0; mi < 2; mi++) {
                uint32_t a = cvta_s(&sA[wm + mi * 16 + (lane & 15)][kk + (lane >> 4) * 8]);
                ldsm_x4(af[mi], a);
            }
            #pragma unroll
            for (int ni = 0; ni < 4; ni++) {
                int r = wn + ni * 8 + (lane & 7);
                uint32_t a = cvta_s(&sB[r][kk + ((lane >> 3) & 1) * 8]);
                ldsm_x2(bf_[ni], a);
            }
            #pragma unroll
            for (int mi = 0; mi < 2; mi++)
                #pragma unroll
                for (int ni = 0; ni < 4; ni++)
                    mma_bf16(acc[mi][ni], af[mi], bf_[ni]);
        }
        __syncthreads();
    }

    const float g = gamma[0];
    const float* invB = inv + (size_t)b * T_;
    #pragma unroll
    for (int mi = 0; mi < 2; mi++) {
        int grow = m0 + wm + mi * 16 + (lane >> 2);
        #pragma unroll
        for (int ni = 0; ni < 4; ni++) {
            int gcol = n0 + wn + ni * 8 + (lane & 3) * 2;
            float2 iv = *reinterpret_cast<const float2*>(&invB[gcol]);
            size_t i0 = (size_t)b * C_ * T_ + (size_t)grow * T_ + gcol;
            size_t i1 = (size_t)b * C_ * T_ + (size_t)(grow + 8) * T_ + gcol;
            float2 x0 = *reinterpret_cast<const float2*>(&x[i0]);
            float2 x1 = *reinterpret_cast<const float2*>(&x[i1]);
            *reinterpret_cast<float2*>(&O[i0]) =
                make_float2(g * acc[mi][ni][0] * iv.x + x0.x, g * acc[mi][ni][1] * iv.y + x0.y);
            *reinterpret_cast<float2*>(&O[i1]) =
                make_float2(g * acc[mi][ni][2] * iv.x + x1.x, g * acc[mi][ni][3] * iv.y + x1.y);
        }
    }
}

// ---------------------------------------------------------------------------
// Launch
// ---------------------------------------------------------------------------
extern "C" void kernel_launch(void* const* d_in, const int* in_sizes, int n_in,
                              void* d_out, int out_size)
{
    const float* x     = (const float*)d_in[0];
    const float* wq    = (const float*)d_in[1];
    const float* bq    = (const float*)d_in[2];
    const float* wk    = (const float*)d_in[3];
    const float* bk    = (const float*)d_in[4];
    const float* wv    = (const float*)d_in[5];
    const float* bv    = (const float*)d_in[6];
    const float* gamma = (const float*)d_in[7];
    float* out = (float*)d_out;

    bf16 *xb, *wqb, *wkb, *wvb, *qb, *kb, *vb, *pb;
    float *rs, *inv;
    cudaGetSymbolAddress((void**)&xb,  g_xb);
    cudaGetSymbolAddress((void**)&wqb, g_wqb);
    cudaGetSymbolAddress((void**)&wkb, g_wkb);
    cudaGetSymbolAddress((void**)&wvb, g_wvb);
    cudaGetSymbolAddress((void**)&qb,  g_qb);
    cudaGetSymbolAddress((void**)&kb,  g_kb);
    cudaGetSymbolAddress((void**)&vb,  g_vb);
    cudaGetSymbolAddress((void**)&pb,  g_p);
    cudaGetSymbolAddress((void**)&rs,  g_rs);
    cudaGetSymbolAddress((void**)&inv, g_inv);

    // converts
    {
        int n4 = (B_ * C_ * T_) / 4;
        f2b_kernel<<<(n4 + 255) / 256, 256>>>(x, xb, n4);
        int nq4 = (CQ_ * C_) / 4, nv4 = (C_ * C_) / 4;
        int tot = nq4 + nq4 + nv4;
        f2b_w<<<(tot + 255) / 256, 256>>>(wq, wqb, nq4, wk, wkb, nq4, wv, wvb, nv4);
    }

    // projections
    proj_mma<<<dim3(T_ / 128, CQ_ / 64, B_), 256>>>(wqb, bq, xb, qb, CQ_, C_);
    proj_mma<<<dim3(T_ / 128, CQ_ / 64, B_), 256>>>(wkb, bk, xb, kb, CQ_, C_);
    proj_mma<<<dim3(T_ / 128, C_  / 64, B_), 256>>>(wvb, bv, xb, vb, C_,  C_);

    // scores + exp + partial row sums (softmax kernel eliminated)
    score_exp<<<dim3(T_ / 128, T_ / 64, B_), 256>>>(qb, kb, pb, rs);

    // row-sum inverse
    inv_rs<<<(B_ * T_) / 256, 256>>>(rs, inv);

    // output GEMM with normalization folded into epilogue
    out_mma<<<dim3(T_ / 128, C_ / 64, B_), 256>>>(vb, pb, inv, x, gamma, out);
}

// round 6
// speedup vs baseline: 1.6978x; 1.3609x over previous
#include <cuda_runtime.h>
#include <cuda_bf16.h>
#include <cstdint>

using bf16 = __nv_bfloat16;

#define B_  8
#define C_  512
#define T_  2048
#define CQ_ 64

// ---------------------------------------------------------------------------
// Device-global scratch
// ---------------------------------------------------------------------------
__device__ bf16  g_xb [B_ * C_ * T_];
__device__ bf16  g_wqb[CQ_ * C_];
__device__ bf16  g_wkb[CQ_ * C_];
__device__ bf16  g_wvb[C_ * C_];
__device__ bf16  g_qb [B_ * CQ_ * T_];
__device__ bf16  g_kb [B_ * CQ_ * T_];
__device__ bf16  g_vb [B_ * C_  * T_];
__device__ bf16  g_p  [(size_t)B_ * T_ * T_];   // unnormalized probs bf16
__device__ float g_rs [B_ * 16 * T_];
__device__ float g_inv[B_ * T_];

// ---------------------------------------------------------------------------
// PTX helpers
// ---------------------------------------------------------------------------
__device__ __forceinline__ uint32_t cvta_s(const void* p) {
    return (uint32_t)__cvta_generic_to_shared(p);
}
__device__ __forceinline__ void ldsm_x4(uint32_t* r, uint32_t a) {
    asm volatile("ldmatrix.sync.aligned.m8n8.x4.shared.b16 {%0,%1,%2,%3},[%4];"
                 : "=r"(r[0]), "=r"(r[1]), "=r"(r[2]), "=r"(r[3]) : "r"(a));
}
__device__ __forceinline__ void ldsm_x4t(uint32_t* r, uint32_t a) {
    asm volatile("ldmatrix.sync.aligned.m8n8.x4.trans.shared.b16 {%0,%1,%2,%3},[%4];"
                 : "=r"(r[0]), "=r"(r[1]), "=r"(r[2]), "=r"(r[3]) : "r"(a));
}
__device__ __forceinline__ void ldsm_x2(uint32_t* r, uint32_t a) {
    asm volatile("ldmatrix.sync.aligned.m8n8.x2.shared.b16 {%0,%1},[%2];"
                 : "=r"(r[0]), "=r"(r[1]) : "r"(a));
}
__device__ __forceinline__ void ldsm_x2t(uint32_t* r, uint32_t a) {
    asm volatile("ldmatrix.sync.aligned.m8n8.x2.trans.shared.b16 {%0,%1},[%2];"
                 : "=r"(r[0]), "=r"(r[1]) : "r"(a));
}
__device__ __forceinline__ void mma_bf16(float* c, const uint32_t* a, const uint32_t* b) {
    asm volatile("mma.sync.aligned.m16n8k16.row.col.f32.bf16.bf16.f32 "
                 "{%0,%1,%2,%3},{%4,%5,%6,%7},{%8,%9},{%0,%1,%2,%3};"
                 : "+f"(c[0]), "+f"(c[1]), "+f"(c[2]), "+f"(c[3])
                 : "r"(a[0]), "r"(a[1]), "r"(a[2]), "r"(a[3]), "r"(b[0]), "r"(b[1]));
}
__device__ __forceinline__ void cp16(uint32_t dst, const void* src) {
    asm volatile("cp.async.ca.shared.global [%0], [%1], 16;" :: "r"(dst), "l"(src));
}
#define CP_COMMIT() asm volatile("cp.async.commit_group;" ::: "memory")
#define CP_WAIT(n)  asm volatile("cp.async.wait_group %0;" :: "n"(n) : "memory")

// ---------------------------------------------------------------------------
// fp32 -> bf16 converts
// ---------------------------------------------------------------------------
__device__ __forceinline__ void cvt4(const float* in, bf16* out, int i) {
    float4 v = *reinterpret_cast<const float4*>(in + (size_t)i * 4);
    __nv_bfloat162 lo = __floats2bfloat162_rn(v.x, v.y);
    __nv_bfloat162 hi = __floats2bfloat162_rn(v.z, v.w);
    uint2 pk;
    pk.x = *reinterpret_cast<uint32_t*>(&lo);
    pk.y = *reinterpret_cast<uint32_t*>(&hi);
    *reinterpret_cast<uint2*>(out + (size_t)i * 4) = pk;
}
__global__ void f2b_kernel(const float* __restrict__ in, bf16* __restrict__ out, int n4) {
    int i = blockIdx.x * blockDim.x + threadIdx.x;
    if (i < n4) cvt4(in, out, i);
}
__global__ void f2b_w(const float* __restrict__ a, bf16* __restrict__ ao, int na4,
                      const float* __restrict__ b, bf16* __restrict__ bo, int nb4,
                      const float* __restrict__ c, bf16* __restrict__ co, int nc4) {
    int i = blockIdx.x * blockDim.x + threadIdx.x;
    if (i < na4)                    cvt4(a, ao, i);
    else if (i < na4 + nb4)         cvt4(b, bo, i - na4);
    else if (i < na4 + nb4 + nc4)   cvt4(c, co, i - na4 - nb4);
}

// ---------------------------------------------------------------------------
// Fused projections: one launch. blockIdx.y: 0=q, 1=k, 2..9=v tiles.
// ---------------------------------------------------------------------------
__global__ void proj_all(const bf16* __restrict__ wq, const float* __restrict__ bq, bf16* __restrict__ q,
                         const bf16* __restrict__ wk, const float* __restrict__ bk, bf16* __restrict__ k,
                         const bf16* __restrict__ wv, const float* __restrict__ bv, bf16* __restrict__ v,
                         const bf16* __restrict__ X)
{
    __shared__ bf16 sA[64][72];
    __shared__ bf16 sB[64][136];

    const int y = blockIdx.y;
    const bf16* W; const float* bias; bf16* Out; int m0; int Mrows;
    if (y == 0)      { W = wq; bias = bq; Out = q; m0 = 0;            Mrows = CQ_; }
    else if (y == 1) { W = wk; bias = bk; Out = k; m0 = 0;            Mrows = CQ_; }
    else             { W = wv; bias = bv; Out = v; m0 = (y - 2) * 64; Mrows = C_;  }

    const int b  = blockIdx.z;
    const int n0 = blockIdx.x * 128;
    const bf16* Xb = X + (size_t)b * C_ * T_;
    bf16*       Ob = Out + (size_t)b * Mrows * T_;

    const int tid  = threadIdx.x;
    const int lane = tid & 31;
    const int w    = tid >> 5;
    const int wm   = (w >> 2) * 32;
    const int wn   = (w & 3) * 32;

    float acc[2][4][4] = {};

    for (int kc = 0; kc < C_; kc += 64) {
        {
            int r = tid >> 3, c = (tid & 7) * 8;
            #pragma unroll
            for (int p = 0; p < 2; p++)
                *reinterpret_cast<uint4*>(&sA[r + p * 32][c]) =
                    *reinterpret_cast<const uint4*>(&W[(size_t)(m0 + r + p * 32) * C_ + kc + c]);
        }
        {
            int r = tid >> 4, c = (tid & 15) * 8;
            #pragma unroll
            for (int p = 0; p < 4; p++)
                *reinterpret_cast<uint4*>(&sB[r + p * 16][c]) =
                    *reinterpret_cast<const uint4*>(&Xb[(size_t)(kc + r + p * 16) * T_ + n0 + c]);
        }
        __syncthreads();

        #pragma unroll
        for (int kk = 0; kk < 64; kk += 16) {
            uint32_t af[2][4], bf_[4][2];
            #pragma unroll
            for (int mi = 0; mi < 2; mi++) {
                uint32_t a = cvta_s(&sA[wm + mi * 16 + (lane & 15)][kk + (lane >> 4) * 8]);
                ldsm_x4(af[mi], a);
            }
            #pragma unroll
            for (int ni = 0; ni < 4; ni++) {
                int r = kk + ((lane >> 3) & 1) * 8 + (lane & 7);
                uint32_t a = cvta_s(&sB[r][wn + ni * 8]);
                ldsm_x2t(bf_[ni], a);
            }
            #pragma unroll
            for (int mi = 0; mi < 2; mi++)
                #pragma unroll
                for (int ni = 0; ni < 4; ni++)
                    mma_bf16(acc[mi][ni], af[mi], bf_[ni]);
        }
        __syncthreads();
    }

    #pragma unroll
    for (int mi = 0; mi < 2; mi++) {
        int grow = m0 + wm + mi * 16 + (lane >> 2);
        float bv0 = bias[grow];
        float bv1 = bias[grow + 8];
        #pragma unroll
        for (int ni = 0; ni < 4; ni++) {
            int gcol = n0 + wn + ni * 8 + (lane & 3) * 2;
            __nv_bfloat162 v0 = __floats2bfloat162_rn(acc[mi][ni][0] + bv0, acc[mi][ni][1] + bv0);
            __nv_bfloat162 v1 = __floats2bfloat162_rn(acc[mi][ni][2] + bv1, acc[mi][ni][3] + bv1);
            *reinterpret_cast<__nv_bfloat162*>(&Ob[(size_t)grow * T_ + gcol]) = v0;
            *reinterpret_cast<__nv_bfloat162*>(&Ob[(size_t)(grow + 8) * T_ + gcol]) = v1;
        }
    }
}

// ---------------------------------------------------------------------------
// Scores + exp (validated round 4)
// ---------------------------------------------------------------------------
__global__ void score_exp(const bf16* __restrict__ Q, const bf16* __restrict__ Km,
                          bf16* __restrict__ P, float* __restrict__ partial)
{
    __shared__ bf16 sA[64][72];
    __shared__ bf16 sB[64][136];
    __shared__ float red[4][64];

    const int b  = blockIdx.z;
    const int n0 = blockIdx.x * 128;
    const int m0 = blockIdx.y * 64;
    const bf16* Qb = Q  + (size_t)b * CQ_ * T_;
    const bf16* Kb = Km + (size_t)b * CQ_ * T_;

    const int tid  = threadIdx.x;
    const int lane = tid & 31;
    const int w    = tid >> 5;
    const int wm   = (w >> 2) * 32;
    const int wn   = (w & 3) * 32;

    {
        int r = tid >> 3, c = (tid & 7) * 8;
        #pragma unroll
        for (int p = 0; p < 2; p++)
            *reinterpret_cast<uint4*>(&sA[r + p * 32][c]) =
                *reinterpret_cast<const uint4*>(&Qb[(size_t)(r + p * 32) * T_ + m0 + c]);
    }
    {
        int r = tid >> 4, c = (tid & 15) * 8;
        #pragma unroll
        for (int p = 0; p < 4; p++)
            *reinterpret_cast<uint4*>(&sB[r + p * 16][c]) =
                *reinterpret_cast<const uint4*>(&Kb[(size_t)(r + p * 16) * T_ + n0 + c]);
    }
    __syncthreads();

    float acc[2][4][4] = {};

    #pragma unroll
    for (int kk = 0; kk < 64; kk += 16) {
        uint32_t af[2][4], bf_[4][2];
        int g = lane >> 3;
        #pragma unroll
        for (int mi = 0; mi < 2; mi++) {
            uint32_t a = cvta_s(&sA[kk + (g >> 1) * 8 + (lane & 7)][wm + mi * 16 + (g & 1) * 8]);
            ldsm_x4t(af[mi], a);
        }
        #pragma unroll
        for (int ni = 0; ni < 4; ni++) {
            int r = kk + ((lane >> 3) & 1) * 8 + (lane & 7);
            uint32_t a = cvta_s(&sB[r][wn + ni * 8]);
            ldsm_x2t(bf_[ni], a);
        }
        #pragma unroll
        for (int mi = 0; mi < 2; mi++)
            #pragma unroll
            for (int ni = 0; ni < 4; ni++)
                mma_bf16(acc[mi][ni], af[mi], bf_[ni]);
    }

    bf16* Pb = P + (size_t)b * T_ * T_;
    float rs[2][2] = {};
    #pragma unroll
    for (int mi = 0; mi < 2; mi++) {
        int grow = m0 + wm + mi * 16 + (lane >> 2);
        #pragma unroll
        for (int ni = 0; ni < 4; ni++) {
            float p0 = __expf(acc[mi][ni][0]);
            float p1 = __expf(acc[mi][ni][1]);
            float p2 = __expf(acc[mi][ni][2]);
            float p3 = __expf(acc[mi][ni][3]);
            rs[mi][0] += p0 + p1;
            rs[mi][1] += p2 + p3;
            int gcol = n0 + wn + ni * 8 + (lane & 3) * 2;
            __nv_bfloat162 lo = __floats2bfloat162_rn(p0, p1);
            __nv_bfloat162 hi = __floats2bfloat162_rn(p2, p3);
            *reinterpret_cast<__nv_bfloat162*>(&Pb[(size_t)grow * T_ + gcol]) = lo;
            *reinterpret_cast<__nv_bfloat162*>(&Pb[(size_t)(grow + 8) * T_ + gcol]) = hi;
        }
    }
    #pragma unroll
    for (int mi = 0; mi < 2; mi++)
        #pragma unroll
        for (int h = 0; h < 2; h++) {
            float v = rs[mi][h];
            v += __shfl_xor_sync(0xffffffffu, v, 1);
            v += __shfl_xor_sync(0xffffffffu, v, 2);
            if ((lane & 3) == 0)
                red[w & 3][wm + mi * 16 + h * 8 + (lane >> 2)] = v;
        }
    __syncthreads();
    if (tid < 64) {
        float tot = red[0][tid] + red[1][tid] + red[2][tid] + red[3][tid];
        partial[((size_t)b * 16 + blockIdx.x) * T_ + m0 + tid] = tot;
    }
}

__global__ void inv_rs(const float* __restrict__ partial, float* __restrict__ inv) {
    int idx = blockIdx.x * 256 + threadIdx.x;
    int b = idx >> 11;
    int t = idx & (T_ - 1);
    const float* p = partial + (size_t)b * 16 * T_ + t;
    float s = 0.0f;
    #pragma unroll
    for (int j = 0; j < 16; j++) s += p[j * T_];
    inv[idx] = 1.0f / s;
}

// ---------------------------------------------------------------------------
// Output GEMM v2: 128(c) x 128(t) tiles, cp.async double-buffered K-chunks of 64.
// O[b,c,t] = gamma * inv[b,t] * sum_s V[b,c,s]*P~[t,s] + x[b,c,t]
// 256 threads = 8 warps (2m x 4n), warp tile 64x32.
// smem: A[2][128][72], B[2][128][72] bf16 (pitch 72 = conflict-free ldsm)
// ---------------------------------------------------------------------------
#define OA0 0u
#define OA1 18432u
#define OB0 36864u
#define OB1 55296u
#define OUT_SMEM 73728u

__device__ __forceinline__ void out_issue_chunk(const bf16* Vb, const bf16* Pb,
                                                int m0, int n0, int kc,
                                                uint32_t sb, int buf, int tid)
{
    const uint32_t aoff = buf ? OA1 : OA0;
    const uint32_t boff = buf ? OB1 : OB0;
    #pragma unroll
    for (int j = 0; j < 4; j++) {
        int u = tid + j * 256;
        int row = u >> 3, c16 = u & 7;
        uint32_t d = sb + aoff + (uint32_t)(row * 144 + c16 * 16);
        cp16(d, &Vb[(size_t)(m0 + row) * T_ + kc + c16 * 8]);
    }
    #pragma unroll
    for (int j = 0; j < 4; j++) {
        int u = tid + j * 256;
        int row = u >> 3, c16 = u & 7;
        uint32_t d = sb + boff + (uint32_t)(row * 144 + c16 * 16);
        cp16(d, &Pb[(size_t)(n0 + row) * T_ + kc + c16 * 8]);
    }
    CP_COMMIT();
}

__global__ void __launch_bounds__(256, 2)
out_mma2(const bf16* __restrict__ V, const bf16* __restrict__ P,
         const float* __restrict__ inv, const float* __restrict__ x,
         const float* __restrict__ gamma, float* __restrict__ O)
{
    extern __shared__ __align__(128) char smem[];
    const uint32_t sb = cvta_s(smem);

    const int b  = blockIdx.z;
    const int n0 = blockIdx.x * 128;   // t
    const int m0 = blockIdx.y * 128;   // c
    const bf16* Vb = V + (size_t)b * C_ * T_;
    const bf16* Pb = P + (size_t)b * T_ * T_;

    const int tid  = threadIdx.x;
    const int lane = tid & 31;
    const int w    = tid >> 5;
    const int wm   = (w >> 2) * 64;    // m warp offset (0 or 64)
    const int wn   = (w & 3) * 32;     // n warp offset

    float acc[4][4][4] = {};

    // prologue: prefetch chunks 0 and 1
    out_issue_chunk(Vb, Pb, m0, n0, 0,  sb, 0, tid);
    out_issue_chunk(Vb, Pb, m0, n0, 64, sb, 1, tid);

    #pragma unroll 1
    for (int ch = 0; ch < 32; ch++) {
        const int buf = ch & 1;
        if (ch < 31) { CP_WAIT(1); } else { CP_WAIT(0); }
        __syncthreads();

        const bf16* sA = reinterpret_cast<const bf16*>(smem + (buf ? OA1 : OA0));
        const bf16* sB = reinterpret_cast<const bf16*>(smem + (buf ? OB1 : OB0));

        #pragma unroll
        for (int kk = 0; kk < 64; kk += 16) {
            uint32_t af[4][4], bf_[4][2];
            #pragma unroll
            for (int mi = 0; mi < 4; mi++) {
                uint32_t a = cvta_s(&sA[(wm + mi * 16 + (lane & 15)) * 72 + kk + (lane >> 4) * 8]);
                ldsm_x4(af[mi], a);
            }
            #pragma unroll
            for (int ni = 0; ni < 4; ni++) {
                uint32_t a = cvta_s(&sB[(wn + ni * 8 + (lane & 7)) * 72 + kk + ((lane >> 3) & 1) * 8]);
                ldsm_x2(bf_[ni], a);
            }
            #pragma unroll
            for (int mi = 0; mi < 4; mi++)
                #pragma unroll
                for (int ni = 0; ni < 4; ni++)
                    mma_bf16(acc[mi][ni], af[mi], bf_[ni]);
        }
        __syncthreads();

        if (ch + 2 < 32)
            out_issue_chunk(Vb, Pb, m0, n0, (ch + 2) * 64, sb, buf, tid);
    }

    const float g = gamma[0];
    const float* invB = inv + (size_t)b * T_;
    #pragma unroll
    for (int mi = 0; mi < 4; mi++) {
        int grow = m0 + wm + mi * 16 + (lane >> 2);
        #pragma unroll
        for (int ni = 0; ni < 4; ni++) {
            int gcol = n0 + wn + ni * 8 + (lane & 3) * 2;
            float2 iv = *reinterpret_cast<const float2*>(&invB[gcol]);
            size_t i0 = (size_t)b * C_ * T_ + (size_t)grow * T_ + gcol;
            size_t i1 = (size_t)b * C_ * T_ + (size_t)(grow + 8) * T_ + gcol;
            float2 x0 = *reinterpret_cast<const float2*>(&x[i0]);
            float2 x1 = *reinterpret_cast<const float2*>(&x[i1]);
            *reinterpret_cast<float2*>(&O[i0]) =
                make_float2(g * acc[mi][ni][0] * iv.x + x0.x, g * acc[mi][ni][1] * iv.y + x0.y);
            *reinterpret_cast<float2*>(&O[i1]) =
                make_float2(g * acc[mi][ni][2] * iv.x + x1.x, g * acc[mi][ni][3] * iv.y + x1.y);
        }
    }
}

// ---------------------------------------------------------------------------
// Launch
// ---------------------------------------------------------------------------
extern "C" void kernel_launch(void* const* d_in, const int* in_sizes, int n_in,
                              void* d_out, int out_size)
{
    const float* x     = (const float*)d_in[0];
    const float* wq    = (const float*)d_in[1];
    const float* bq    = (const float*)d_in[2];
    const float* wk    = (const float*)d_in[3];
    const float* bk    = (const float*)d_in[4];
    const float* wv    = (const float*)d_in[5];
    const float* bv    = (const float*)d_in[6];
    const float* gamma = (const float*)d_in[7];
    float* out = (float*)d_out;

    bf16 *xb, *wqb, *wkb, *wvb, *qb, *kb, *vb, *pb;
    float *rs, *inv;
    cudaGetSymbolAddress((void**)&xb,  g_xb);
    cudaGetSymbolAddress((void**)&wqb, g_wqb);
    cudaGetSymbolAddress((void**)&wkb, g_wkb);
    cudaGetSymbolAddress((void**)&wvb, g_wvb);
    cudaGetSymbolAddress((void**)&qb,  g_qb);
    cudaGetSymbolAddress((void**)&kb,  g_kb);
    cudaGetSymbolAddress((void**)&vb,  g_vb);
    cudaGetSymbolAddress((void**)&pb,  g_p);
    cudaGetSymbolAddress((void**)&rs,  g_rs);
    cudaGetSymbolAddress((void**)&inv, g_inv);

    cudaFuncSetAttribute(out_mma2, cudaFuncAttributeMaxDynamicSharedMemorySize, OUT_SMEM);

    // converts
    {
        int n4 = (B_ * C_ * T_) / 4;
        f2b_kernel<<<(n4 + 255) / 256, 256>>>(x, xb, n4);
        int nq4 = (CQ_ * C_) / 4, nv4 = (C_ * C_) / 4;
        int tot = nq4 + nq4 + nv4;
        f2b_w<<<(tot + 255) / 256, 256>>>(wq, wqb, nq4, wk, wkb, nq4, wv, wvb, nv4);
    }

    // all three projections in one launch
    proj_all<<<dim3(T_ / 128, 10, B_), 256>>>(wqb, bq, qb, wkb, bk, kb, wvb, bv, vb, xb);

    // scores + exp + partial row sums
    score_exp<<<dim3(T_ / 128, T_ / 64, B_), 256>>>(qb, kb, pb, rs);

    // row-sum inverse
    inv_rs<<<(B_ * T_) / 256, 256>>>(rs, inv);

    // output GEMM: 128x128 tiles, cp.async pipelined
    out_mma2<<<dim3(T_ / 128, C_ / 128, B_), 256, OUT_SMEM>>>(vb, pb, inv, x, gamma, out);
}

// round 7
// speedup vs baseline: 1.7451x; 1.0279x over previous
#include <cuda_runtime.h>
#include <cuda_bf16.h>
#include <cstdint>

using bf16 = __nv_bfloat16;

#define B_  8
#define C_  512
#define T_  2048
#define CQ_ 64

// ---------------------------------------------------------------------------
// Device-global scratch
// ---------------------------------------------------------------------------
__device__ bf16  g_xb [B_ * C_ * T_];
__device__ bf16  g_wqb[CQ_ * C_];
__device__ bf16  g_wkb[CQ_ * C_];
__device__ bf16  g_wvb[C_ * C_];
__device__ bf16  g_qb [B_ * CQ_ * T_];
__device__ bf16  g_kb [B_ * CQ_ * T_];
__device__ bf16  g_vb [B_ * C_  * T_];
__device__ bf16  g_p  [(size_t)B_ * T_ * T_];   // unnormalized probs bf16
__device__ float g_rs [B_ * 16 * T_];
__device__ float g_inv[B_ * T_];

// ---------------------------------------------------------------------------
// PTX helpers
// ---------------------------------------------------------------------------
__device__ __forceinline__ uint32_t cvta_s(const void* p) {
    return (uint32_t)__cvta_generic_to_shared(p);
}
__device__ __forceinline__ void ldsm_x4(uint32_t* r, uint32_t a) {
    asm volatile("ldmatrix.sync.aligned.m8n8.x4.shared.b16 {%0,%1,%2,%3},[%4];"
                 : "=r"(r[0]), "=r"(r[1]), "=r"(r[2]), "=r"(r[3]) : "r"(a));
}
__device__ __forceinline__ void ldsm_x4t(uint32_t* r, uint32_t a) {
    asm volatile("ldmatrix.sync.aligned.m8n8.x4.trans.shared.b16 {%0,%1,%2,%3},[%4];"
                 : "=r"(r[0]), "=r"(r[1]), "=r"(r[2]), "=r"(r[3]) : "r"(a));
}
__device__ __forceinline__ void ldsm_x2t(uint32_t* r, uint32_t a) {
    asm volatile("ldmatrix.sync.aligned.m8n8.x2.trans.shared.b16 {%0,%1},[%2];"
                 : "=r"(r[0]), "=r"(r[1]) : "r"(a));
}
__device__ __forceinline__ void mma_bf16(float* c, const uint32_t* a, const uint32_t* b) {
    asm volatile("mma.sync.aligned.m16n8k16.row.col.f32.bf16.bf16.f32 "
                 "{%0,%1,%2,%3},{%4,%5,%6,%7},{%8,%9},{%0,%1,%2,%3};"
                 : "+f"(c[0]), "+f"(c[1]), "+f"(c[2]), "+f"(c[3])
                 : "r"(a[0]), "r"(a[1]), "r"(a[2]), "r"(a[3]), "r"(b[0]), "r"(b[1]));
}
__device__ __forceinline__ void cp16(uint32_t dst, const void* src) {
    asm volatile("cp.async.ca.shared.global [%0], [%1], 16;" :: "r"(dst), "l"(src));
}
#define CP_COMMIT() asm volatile("cp.async.commit_group;" ::: "memory")
#define CP_WAIT(n)  asm volatile("cp.async.wait_group %0;" :: "n"(n) : "memory")

// ---------------------------------------------------------------------------
// fp32 -> bf16 converts
// ---------------------------------------------------------------------------
__device__ __forceinline__ void cvt4(const float* in, bf16* out, int i) {
    float4 v = *reinterpret_cast<const float4*>(in + (size_t)i * 4);
    __nv_bfloat162 lo = __floats2bfloat162_rn(v.x, v.y);
    __nv_bfloat162 hi = __floats2bfloat162_rn(v.z, v.w);
    uint2 pk;
    pk.x = *reinterpret_cast<uint32_t*>(&lo);
    pk.y = *reinterpret_cast<uint32_t*>(&hi);
    *reinterpret_cast<uint2*>(out + (size_t)i * 4) = pk;
}
__global__ void f2b_kernel(const float* __restrict__ in, bf16* __restrict__ out, int n4) {
    int i = blockIdx.x * blockDim.x + threadIdx.x;
    if (i < n4) cvt4(in, out, i);
}
__global__ void f2b_w(const float* __restrict__ a, bf16* __restrict__ ao, int na4,
                      const float* __restrict__ b, bf16* __restrict__ bo, int nb4,
                      const float* __restrict__ c, bf16* __restrict__ co, int nc4) {
    int i = blockIdx.x * blockDim.x + threadIdx.x;
    if (i < na4)                    cvt4(a, ao, i);
    else if (i < na4 + nb4)         cvt4(b, bo, i - na4);
    else if (i < na4 + nb4 + nc4)   cvt4(c, co, i - na4 - nb4);
}

// ---------------------------------------------------------------------------
// Fused projections (validated): blockIdx.y: 0=q, 1=k, 2..9=v tiles.
// ---------------------------------------------------------------------------
__global__ void proj_all(const bf16* __restrict__ wq, const float* __restrict__ bq, bf16* __restrict__ q,
                         const bf16* __restrict__ wk, const float* __restrict__ bk, bf16* __restrict__ k,
                         const bf16* __restrict__ wv, const float* __restrict__ bv, bf16* __restrict__ v,
                         const bf16* __restrict__ X)
{
    __shared__ bf16 sA[64][72];
    __shared__ bf16 sB[64][136];

    const int y = blockIdx.y;
    const bf16* W; const float* bias; bf16* Out; int m0; int Mrows;
    if (y == 0)      { W = wq; bias = bq; Out = q; m0 = 0;            Mrows = CQ_; }
    else if (y == 1) { W = wk; bias = bk; Out = k; m0 = 0;            Mrows = CQ_; }
    else             { W = wv; bias = bv; Out = v; m0 = (y - 2) * 64; Mrows = C_;  }

    const int b  = blockIdx.z;
    const int n0 = blockIdx.x * 128;
    const bf16* Xb = X + (size_t)b * C_ * T_;
    bf16*       Ob = Out + (size_t)b * Mrows * T_;

    const int tid  = threadIdx.x;
    const int lane = tid & 31;
    const int w    = tid >> 5;
    const int wm   = (w >> 2) * 32;
    const int wn   = (w & 3) * 32;

    float acc[2][4][4] = {};

    for (int kc = 0; kc < C_; kc += 64) {
        {
            int r = tid >> 3, c = (tid & 7) * 8;
            #pragma unroll
            for (int p = 0; p < 2; p++)
                *reinterpret_cast<uint4*>(&sA[r + p * 32][c]) =
                    *reinterpret_cast<const uint4*>(&W[(size_t)(m0 + r + p * 32) * C_ + kc + c]);
        }
        {
            int r = tid >> 4, c = (tid & 15) * 8;
            #pragma unroll
            for (int p = 0; p < 4; p++)
                *reinterpret_cast<uint4*>(&sB[r + p * 16][c]) =
                    *reinterpret_cast<const uint4*>(&Xb[(size_t)(kc + r + p * 16) * T_ + n0 + c]);
        }
        __syncthreads();

        #pragma unroll
        for (int kk = 0; kk < 64; kk += 16) {
            uint32_t af[2][4], bf_[4][2];
            #pragma unroll
            for (int mi = 0; mi < 2; mi++) {
                uint32_t a = cvta_s(&sA[wm + mi * 16 + (lane & 15)][kk + (lane >> 4) * 8]);
                ldsm_x4(af[mi], a);
            }
            #pragma unroll
            for (int ni = 0; ni < 4; ni++) {
                int r = kk + ((lane >> 3) & 1) * 8 + (lane & 7);
                uint32_t a = cvta_s(&sB[r][wn + ni * 8]);
                ldsm_x2t(bf_[ni], a);
            }
            #pragma unroll
            for (int mi = 0; mi < 2; mi++)
                #pragma unroll
                for (int ni = 0; ni < 4; ni++)
                    mma_bf16(acc[mi][ni], af[mi], bf_[ni]);
        }
        __syncthreads();
    }

    #pragma unroll
    for (int mi = 0; mi < 2; mi++) {
        int grow = m0 + wm + mi * 16 + (lane >> 2);
        float bv0 = bias[grow];
        float bv1 = bias[grow + 8];
        #pragma unroll
        for (int ni = 0; ni < 4; ni++) {
            int gcol = n0 + wn + ni * 8 + (lane & 3) * 2;
            __nv_bfloat162 v0 = __floats2bfloat162_rn(acc[mi][ni][0] + bv0, acc[mi][ni][1] + bv0);
            __nv_bfloat162 v1 = __floats2bfloat162_rn(acc[mi][ni][2] + bv1, acc[mi][ni][3] + bv1);
            *reinterpret_cast<__nv_bfloat162*>(&Ob[(size_t)grow * T_ + gcol]) = v0;
            *reinterpret_cast<__nv_bfloat162*>(&Ob[(size_t)(grow + 8) * T_ + gcol]) = v1;
        }
    }
}

// ---------------------------------------------------------------------------
// Scores + exp v2: 128(t) x 128(s) tile, 256 threads = 8 warps (2m x 4n),
// warp tile 64x32. P staged through smem for vectorized stores.
// ---------------------------------------------------------------------------
__global__ void __launch_bounds__(256)
score_exp2(const bf16* __restrict__ Q, const bf16* __restrict__ Km,
           bf16* __restrict__ P, float* __restrict__ partial)
{
    __shared__ __align__(16) char sm[34816 + 2048];
    bf16*  sQ  = reinterpret_cast<bf16*>(sm);            // [64][136] (o, t)
    bf16*  sK  = reinterpret_cast<bf16*>(sm + 17408);    // [64][136] (o, s)
    bf16*  stg = reinterpret_cast<bf16*>(sm);            // [128][136] overlays Q/K
    float* red = reinterpret_cast<float*>(sm + 34816);   // [4][128]

    const int b  = blockIdx.z;
    const int s0 = blockIdx.x * 128;
    const int t0 = blockIdx.y * 128;
    const bf16* Qb = Q  + (size_t)b * CQ_ * T_;
    const bf16* Kb = Km + (size_t)b * CQ_ * T_;

    const int tid  = threadIdx.x;
    const int lane = tid & 31;
    const int w    = tid >> 5;
    const int wm   = (w >> 2) * 64;   // t warp offset (0 or 64)
    const int wn   = (w & 3) * 32;    // s warp offset

    // load Q [64 o][128 t] and K [64 o][128 s]
    #pragma unroll
    for (int i = 0; i < 4; i++) {
        int u = tid + i * 256;
        int r = u >> 4, c = (u & 15) * 8;
        *reinterpret_cast<uint4*>(&sQ[r * 136 + c]) =
            *reinterpret_cast<const uint4*>(&Qb[(size_t)r * T_ + t0 + c]);
        *reinterpret_cast<uint4*>(&sK[r * 136 + c]) =
            *reinterpret_cast<const uint4*>(&Kb[(size_t)r * T_ + s0 + c]);
    }
    __syncthreads();

    float acc[4][4][4] = {};

    #pragma unroll
    for (int kk = 0; kk < 64; kk += 16) {
        uint32_t af[4][4], bf_[4][2];
        const int g = lane >> 3;
        #pragma unroll
        for (int mi = 0; mi < 4; mi++) {
            uint32_t a = cvta_s(&sQ[(kk + (g >> 1) * 8 + (lane & 7)) * 136 +
                                    wm + mi * 16 + (g & 1) * 8]);
            ldsm_x4t(af[mi], a);
        }
        // B pairs: one x4t yields frags ni=2p and ni=2p+1
        #pragma unroll
        for (int p = 0; p < 2; p++) {
            uint32_t tmp[4];
            uint32_t a = cvta_s(&sK[(kk + ((lane >> 3) & 1) * 8 + (lane & 7)) * 136 +
                                    wn + p * 16 + (lane >> 4) * 8]);
            ldsm_x4t(tmp, a);
            bf_[2 * p][0] = tmp[0]; bf_[2 * p][1] = tmp[1];
            bf_[2 * p + 1][0] = tmp[2]; bf_[2 * p + 1][1] = tmp[3];
        }
        #pragma unroll
        for (int mi = 0; mi < 4; mi++)
            #pragma unroll
            for (int ni = 0; ni < 4; ni++)
                mma_bf16(acc[mi][ni], af[mi], bf_[ni]);
    }
    __syncthreads();   // all warps done reading sQ/sK before stg overwrite

    // exp -> staged bf16 P + partial row sums
    float rs[4][2] = {};
    #pragma unroll
    for (int mi = 0; mi < 4; mi++) {
        int r0 = wm + mi * 16 + (lane >> 2);
        #pragma unroll
        for (int ni = 0; ni < 4; ni++) {
            float p0 = __expf(acc[mi][ni][0]);
            float p1 = __expf(acc[mi][ni][1]);
            float p2 = __expf(acc[mi][ni][2]);
            float p3 = __expf(acc[mi][ni][3]);
            rs[mi][0] += p0 + p1;
            rs[mi][1] += p2 + p3;
            int cc = wn + ni * 8 + (lane & 3) * 2;
            __nv_bfloat162 lo = __floats2bfloat162_rn(p0, p1);
            __nv_bfloat162 hi = __floats2bfloat162_rn(p2, p3);
            *reinterpret_cast<__nv_bfloat162*>(&stg[r0 * 136 + cc]) = lo;
            *reinterpret_cast<__nv_bfloat162*>(&stg[(r0 + 8) * 136 + cc]) = hi;
        }
    }
    // row-sum partials: reduce over lane&3, then across 4 n-warps via red
    #pragma unroll
    for (int mi = 0; mi < 4; mi++)
        #pragma unroll
        for (int h = 0; h < 2; h++) {
            float v = rs[mi][h];
            v += __shfl_xor_sync(0xffffffffu, v, 1);
            v += __shfl_xor_sync(0xffffffffu, v, 2);
            if ((lane & 3) == 0)
                red[(w & 3) * 128 + wm + mi * 16 + h * 8 + (lane >> 2)] = v;
        }
    __syncthreads();

    // vectorized P store: 128 rows x 256B
    bf16* Pb = P + (size_t)b * T_ * T_;
    #pragma unroll
    for (int j = 0; j < 8; j++) {
        int u = tid + j * 256;
        int row = u >> 4, c = (u & 15) * 8;
        *reinterpret_cast<uint4*>(&Pb[(size_t)(t0 + row) * T_ + s0 + c]) =
            *reinterpret_cast<const uint4*>(&stg[row * 136 + c]);
    }
    if (tid < 128) {
        float tot = red[tid] + red[128 + tid] + red[256 + tid] + red[384 + tid];
        partial[((size_t)b * 16 + blockIdx.x) * T_ + t0 + tid] = tot;
    }
}

__global__ void inv_rs(const float* __restrict__ partial, float* __restrict__ inv) {
    int idx = blockIdx.x * 256 + threadIdx.x;
    int b = idx >> 11;
    int t = idx & (T_ - 1);
    const float* p = partial + (size_t)b * 16 * T_ + t;
    float s = 0.0f;
    #pragma unroll
    for (int j = 0; j < 16; j++) s += p[j * T_];
    inv[idx] = 1.0f / s;
}

// ---------------------------------------------------------------------------
// Output GEMM: 128(c) x 128(t) tiles, cp.async double-buffered, B ldsm paired.
// ---------------------------------------------------------------------------
#define OA0 0u
#define OA1 18432u
#define OB0 36864u
#define OB1 55296u
#define OUT_SMEM 73728u

__device__ __forceinline__ void out_issue_chunk(const bf16* Vb, const bf16* Pb,
                                                int m0, int n0, int kc,
                                                uint32_t sb, int buf, int tid)
{
    const uint32_t aoff = buf ? OA1 : OA0;
    const uint32_t boff = buf ? OB1 : OB0;
    #pragma unroll
    for (int j = 0; j < 4; j++) {
        int u = tid + j * 256;
        int row = u >> 3, c16 = u & 7;
        uint32_t d = sb + aoff + (uint32_t)(row * 144 + c16 * 16);
        cp16(d, &Vb[(size_t)(m0 + row) * T_ + kc + c16 * 8]);
    }
    #pragma unroll
    for (int j = 0; j < 4; j++) {
        int u = tid + j * 256;
        int row = u >> 3, c16 = u & 7;
        uint32_t d = sb + boff + (uint32_t)(row * 144 + c16 * 16);
        cp16(d, &Pb[(size_t)(n0 + row) * T_ + kc + c16 * 8]);
    }
    CP_COMMIT();
}

__global__ void __launch_bounds__(256, 2)
out_mma2(const bf16* __restrict__ V, const bf16* __restrict__ P,
         const float* __restrict__ inv, const float* __restrict__ x,
         const float* __restrict__ gamma, float* __restrict__ O)
{
    extern __shared__ __align__(128) char smem[];
    const uint32_t sb = cvta_s(smem);

    const int b  = blockIdx.z;
    const int n0 = blockIdx.x * 128;   // t
    const int m0 = blockIdx.y * 128;   // c
    const bf16* Vb = V + (size_t)b * C_ * T_;
    const bf16* Pb = P + (size_t)b * T_ * T_;

    const int tid  = threadIdx.x;
    const int lane = tid & 31;
    const int w    = tid >> 5;
    const int wm   = (w >> 2) * 64;
    const int wn   = (w & 3) * 32;

    float acc[4][4][4] = {};

    out_issue_chunk(Vb, Pb, m0, n0, 0,  sb, 0, tid);
    out_issue_chunk(Vb, Pb, m0, n0, 64, sb, 1, tid);

    #pragma unroll 1
    for (int ch = 0; ch < 32; ch++) {
        const int buf = ch & 1;
        if (ch < 31) { CP_WAIT(1); } else { CP_WAIT(0); }
        __syncthreads();

        const bf16* sA = reinterpret_cast<const bf16*>(smem + (buf ? OA1 : OA0));
        const bf16* sB = reinterpret_cast<const bf16*>(smem + (buf ? OB1 : OB0));

        #pragma unroll
        for (int kk = 0; kk < 64; kk += 16) {
            uint32_t af[4][4], bf_[4][2];
            #pragma unroll
            for (int mi = 0; mi < 4; mi++) {
                uint32_t a = cvta_s(&sA[(wm + mi * 16 + (lane & 15)) * 72 + kk + (lane >> 4) * 8]);
                ldsm_x4(af[mi], a);
            }
            // B pairs: one x4 yields frags ni=2p and ni=2p+1
            #pragma unroll
            for (int p = 0; p < 2; p++) {
                uint32_t tmp[4];
                uint32_t a = cvta_s(&sB[(wn + p * 16 + (lane >> 4) * 8 + (lane & 7)) * 72 +
                                        kk + ((lane >> 3) & 1) * 8]);
                ldsm_x4(tmp, a);
                bf_[2 * p][0] = tmp[0]; bf_[2 * p][1] = tmp[1];
                bf_[2 * p + 1][0] = tmp[2]; bf_[2 * p + 1][1] = tmp[3];
            }
            #pragma unroll
            for (int mi = 0; mi < 4; mi++)
                #pragma unroll
                for (int ni = 0; ni < 4; ni++)
                    mma_bf16(acc[mi][ni], af[mi], bf_[ni]);
        }
        __syncthreads();

        if (ch + 2 < 32)
            out_issue_chunk(Vb, Pb, m0, n0, (ch + 2) * 64, sb, buf, tid);
    }

    const float g = gamma[0];
    const float* invB = inv + (size_t)b * T_;
    #pragma unroll
    for (int mi = 0; mi < 4; mi++) {
        int grow = m0 + wm + mi * 16 + (lane >> 2);
        #pragma unroll
        for (int ni = 0; ni < 4; ni++) {
            int gcol = n0 + wn + ni * 8 + (lane & 3) * 2;
            float2 iv = *reinterpret_cast<const float2*>(&invB[gcol]);
            size_t i0 = (size_t)b * C_ * T_ + (size_t)grow * T_ + gcol;
            size_t i1 = (size_t)b * C_ * T_ + (size_t)(grow + 8) * T_ + gcol;
            float2 x0 = *reinterpret_cast<const float2*>(&x[i0]);
            float2 x1 = *reinterpret_cast<const float2*>(&x[i1]);
            *reinterpret_cast<float2*>(&O[i0]) =
                make_float2(g * acc[mi][ni][0] * iv.x + x0.x, g * acc[mi][ni][1] * iv.y + x0.y);
            *reinterpret_cast<float2*>(&O[i1]) =
                make_float2(g * acc[mi][ni][2] * iv.x + x1.x, g * acc[mi][ni][3] * iv.y + x1.y);
        }
    }
}

// ---------------------------------------------------------------------------
// Launch
// ---------------------------------------------------------------------------
extern "C" void kernel_launch(void* const* d_in, const int* in_sizes, int n_in,
                              void* d_out, int out_size)
{
    const float* x     = (const float*)d_in[0];
    const float* wq    = (const float*)d_in[1];
    const float* bq    = (const float*)d_in[2];
    const float* wk    = (const float*)d_in[3];
    const float* bk    = (const float*)d_in[4];
    const float* wv    = (const float*)d_in[5];
    const float* bv    = (const float*)d_in[6];
    const float* gamma = (const float*)d_in[7];
    float* out = (float*)d_out;

    bf16 *xb, *wqb, *wkb, *wvb, *qb, *kb, *vb, *pb;
    float *rs, *inv;
    cudaGetSymbolAddress((void**)&xb,  g_xb);
    cudaGetSymbolAddress((void**)&wqb, g_wqb);
    cudaGetSymbolAddress((void**)&wkb, g_wkb);
    cudaGetSymbolAddress((void**)&wvb, g_wvb);
    cudaGetSymbolAddress((void**)&qb,  g_qb);
    cudaGetSymbolAddress((void**)&kb,  g_kb);
    cudaGetSymbolAddress((void**)&vb,  g_vb);
    cudaGetSymbolAddress((void**)&pb,  g_p);
    cudaGetSymbolAddress((void**)&rs,  g_rs);
    cudaGetSymbolAddress((void**)&inv, g_inv);

    cudaFuncSetAttribute(out_mma2, cudaFuncAttributeMaxDynamicSharedMemorySize, OUT_SMEM);

    // converts
    {
        int n4 = (B_ * C_ * T_) / 4;
        f2b_kernel<<<(n4 + 255) / 256, 256>>>(x, xb, n4);
        int nq4 = (CQ_ * C_) / 4, nv4 = (C_ * C_) / 4;
        int tot = nq4 + nq4 + nv4;
        f2b_w<<<(tot + 255) / 256, 256>>>(wq, wqb, nq4, wk, wkb, nq4, wv, wvb, nv4);
    }

    // all three projections in one launch
    proj_all<<<dim3(T_ / 128, 10, B_), 256>>>(wqb, bq, qb, wkb, bk, kb, wvb, bv, vb, xb);

    // scores + exp + partial row sums (128x128 tiles)
    score_exp2<<<dim3(T_ / 128, T_ / 128, B_), 256>>>(qb, kb, pb, rs);

    // row-sum inverse
    inv_rs<<<(B_ * T_) / 256, 256>>>(rs, inv);

    // output GEMM
    out_mma2<<<dim3(T_ / 128, C_ / 128, B_), 256, OUT_SMEM>>>(vb, pb, inv, x, gamma, out);
}